// round 6
// baseline (speedup 1.0000x reference)
#include <cuda_runtime.h>
#include <cstddef>

// Problem constants (fixed by the reference)
constexpr int CB   = 64;    // batch
constexpr int CP   = 2048;  // points
constexpr int CK   = 16;    // neighbors
constexpr int CDIM = 3;
constexpr int CNC  = 16;    // rbf centers
constexpr int CSFD = 64;    // spatial feature dim
constexpr int COUT = 64;    // output features

constexpr int PTS     = 32;   // points per block
constexpr int THREADS = 256;  // 8 warps; phase 1: 2 pts/warp x 2 passes
constexpr int FPP     = CK * CDIM;  // 48 floats of features per point

__global__ __launch_bounds__(THREADS, 4)
void rbfn_fused_kernel(const float* __restrict__ features,
                       const float* __restrict__ spatial,
                       const float* __restrict__ centers,
                       const float* __restrict__ rbfw,
                       const float* __restrict__ w,
                       float* __restrict__ out)
{
    __shared__ float w_sh[CSFD * COUT];        // 16 KB : w[b] slice
    __shared__ float rbfn_sh[CNC * CSFD];      // 4 KB
    __shared__ float cen_sh[CDIM * CNC];       // 192 B
    __shared__ float x_sh[PTS * CSFD];         // 8 KB : fused x = fl * sp_sum
    __shared__ float feat_sh[PTS * CK * 4];    // 8 KB : features padded to float4/k

    const int tid = threadIdx.x;
    const int b   = blockIdx.y;
    const int p0  = blockIdx.x * PTS;

    // ---- stage per-batch weight slice + constants + features into smem ----
    {
        const float4* wsrc = reinterpret_cast<const float4*>(w + (size_t)b * CSFD * COUT);
        float4* wdst = reinterpret_cast<float4*>(w_sh);
        #pragma unroll
        for (int i = 0; i < (CSFD * COUT / 4) / THREADS; i++)   // 4 iters
            wdst[tid + i * THREADS] = wsrc[tid + i * THREADS];

        reinterpret_cast<float4*>(rbfn_sh)[tid] =
            reinterpret_cast<const float4*>(rbfw)[tid];   // 256 float4 exactly

        // features: 32 pts x 48 floats = 384 float4, scatter to padded [pt][k][4]
        const float4* fsrc = reinterpret_cast<const float4*>(
            features + ((size_t)b * CP + p0) * FPP);
        #pragma unroll
        for (int i = tid; i < PTS * FPP / 4; i += THREADS) {
            float4 v = fsrc[i];
            int f0 = 4 * i;
            #pragma unroll
            for (int e = 0; e < 4; e++) {
                int f  = f0 + e;
                int pt = f / FPP;
                int r  = f - pt * FPP;
                int k  = r / 3;
                int d  = r - k * 3;
                float val = (e == 0) ? v.x : (e == 1) ? v.y : (e == 2) ? v.z : v.w;
                feat_sh[(pt * CK + k) * 4 + d] = val;
            }
        }

        if (tid < CDIM * CNC) cen_sh[tid] = centers[tid];
    }
    __syncthreads();

    const int warp = tid >> 5;
    const int lane = tid & 31;
    const int cg   = lane & 15;   // column group (s = 4*cg..4*cg+3) AND center id
    const int half = lane >> 4;   // which half of the K rows this lane covers

    const float c0 = cen_sh[0 * CNC + cg];
    const float c1 = cen_sh[1 * CNC + cg];
    const float c2 = cen_sh[2 * CNC + cg];

    // ---- Phase 1: two passes of 2 points per warp (4 pts/warp total) ----
    #pragma unroll
    for (int pass = 0; pass < 2; pass++) {
        const int ptb = warp * 4 + pass * 2;   // local point base for this pass

        // --- 1a: spatial sums, 2 points interleaved ---
        float sx[2], sy[2], sz[2], sw[2];
        #pragma unroll
        for (int j = 0; j < 2; j++) { sx[j] = sy[j] = sz[j] = sw[j] = 0.f; }

        const float4* spv = reinterpret_cast<const float4*>(
            spatial + ((size_t)b * CP + p0 + ptb) * (CK * CSFD));
        #pragma unroll
        for (int i = 0; i < 8; i++) {
            #pragma unroll
            for (int j = 0; j < 2; j++) {
                float4 v = spv[j * 256 + i * 32 + lane];
                sx[j] += v.x; sy[j] += v.y; sz[j] += v.z; sw[j] += v.w;
            }
        }
        #pragma unroll
        for (int j = 0; j < 2; j++) {
            sx[j] += __shfl_xor_sync(0xffffffffu, sx[j], 16);
            sy[j] += __shfl_xor_sync(0xffffffffu, sy[j], 16);
            sz[j] += __shfl_xor_sync(0xffffffffu, sz[j], 16);
            sw[j] += __shfl_xor_sync(0xffffffffu, sw[j], 16);
        }

        // --- 1b: RBF sums. lane -> center cg, covers 8 k's of its half ---
        float racc[2] = {0.f, 0.f};
        #pragma unroll
        for (int i = 0; i < 8; i++) {
            const int k = 2 * i + half;
            #pragma unroll
            for (int j = 0; j < 2; j++) {
                float4 fv = reinterpret_cast<const float4*>(feat_sh)[(ptb + j) * CK + k];
                float d0 = fv.x - c0;
                float d1 = fv.y - c1;
                float d2 = fv.z - c2;
                float dn2 = d0 * d0 + d1 * d1 + d2 * d2;
                racc[j] += __expf(dn2 * -12.5f);   // 1/0.08 = 12.5
            }
        }
        #pragma unroll
        for (int j = 0; j < 2; j++)
            racc[j] += __shfl_xor_sync(0xffffffffu, racc[j], 16);
        // lane c (and c+16) now holds rbf_sum for center c

        // --- 1c: feature layer, rbfn rows hoisted across the 2 points ---
        float flx[2] = {0.f, 0.f}, fly[2] = {0.f, 0.f};
        float flz[2] = {0.f, 0.f}, flw[2] = {0.f, 0.f};
        #pragma unroll
        for (int cc = 0; cc < 4; cc++) {
            float4 wv[4];
            #pragma unroll
            for (int q = 0; q < 4; q++)
                wv[q] = reinterpret_cast<const float4*>(rbfn_sh)[(4 * cc + q) * 16 + cg];
            #pragma unroll
            for (int j = 0; j < 2; j++) {
                #pragma unroll
                for (int q = 0; q < 4; q++) {
                    float rv = __shfl_sync(0xffffffffu, racc[j], 4 * cc + q);
                    flx[j] += rv * wv[q].x; fly[j] += rv * wv[q].y;
                    flz[j] += rv * wv[q].z; flw[j] += rv * wv[q].w;
                }
            }
        }
        #pragma unroll
        for (int j = 0; j < 2; j++) {
            if (half == 0) {
                float4 xv;
                xv.x = flx[j] * sx[j]; xv.y = fly[j] * sy[j];
                xv.z = flz[j] * sz[j]; xv.w = flw[j] * sw[j];
                reinterpret_cast<float4*>(x_sh)[(ptb + j) * 16 + cg] = xv;
            }
        }
    }
    __syncthreads();

    // ---- Phase 2: out[pt][o] = sum_s x[pt][s] * w_sh[s][o], 8 pts/thread ----
    const int o  = tid & 63;
    const int pg = tid >> 6;   // 0..3, each group handles 8 points

    float acc[8];
    #pragma unroll
    for (int jj = 0; jj < 8; jj++) acc[jj] = 0.f;

    #pragma unroll
    for (int sq = 0; sq < CSFD / 4; sq++) {
        float w0 = w_sh[(4 * sq + 0) * COUT + o];
        float w1 = w_sh[(4 * sq + 1) * COUT + o];
        float w2 = w_sh[(4 * sq + 2) * COUT + o];
        float w3 = w_sh[(4 * sq + 3) * COUT + o];
        #pragma unroll
        for (int jj = 0; jj < 8; jj++) {
            // warp-uniform address -> smem broadcast (1 wavefront)
            float4 xv = reinterpret_cast<const float4*>(x_sh)[(pg * 8 + jj) * 16 + sq];
            acc[jj] += xv.x * w0 + xv.y * w1 + xv.z * w2 + xv.w * w3;
        }
    }

    float* ob = out + ((size_t)b * CP + p0) * COUT;
    #pragma unroll
    for (int jj = 0; jj < 8; jj++)
        ob[(size_t)(pg * 8 + jj) * COUT + o] = acc[jj];
}

extern "C" void kernel_launch(void* const* d_in, const int* in_sizes, int n_in,
                              void* d_out, int out_size)
{
    const float* features = (const float*)d_in[0];
    const float* spatial  = (const float*)d_in[1];
    const float* centers  = (const float*)d_in[2];
    const float* rbfw     = (const float*)d_in[3];
    const float* w        = (const float*)d_in[4];
    // d_in[5] is K (=16), fixed at compile time
    float* out = (float*)d_out;

    dim3 grid(CP / PTS, CB);
    rbfn_fused_kernel<<<grid, THREADS>>>(features, spatial, centers, rbfw, w, out);
}

// round 8
// speedup vs baseline: 1.0055x; 1.0055x over previous
#include <cuda_runtime.h>
#include <cstddef>

// Problem constants (fixed by the reference)
constexpr int CB   = 64;    // batch
constexpr int CP   = 2048;  // points
constexpr int CK   = 16;    // neighbors
constexpr int CDIM = 3;
constexpr int CNC  = 16;    // rbf centers
constexpr int CSFD = 64;    // spatial feature dim
constexpr int COUT = 64;    // output features

constexpr int PTS     = 32;   // points per block
constexpr int THREADS = 256;  // 8 warps; phase 1: 2 pts/warp x 2 passes
constexpr int FPP     = CK * CDIM;  // 48 floats of features per point

__global__ __launch_bounds__(THREADS, 4)
void rbfn_fused_kernel(const float* __restrict__ features,
                       const float* __restrict__ spatial,
                       const float* __restrict__ centers,
                       const float* __restrict__ rbfw,
                       const float* __restrict__ w,
                       float* __restrict__ out)
{
    __shared__ float w_sh[CSFD * COUT];        // 16 KB : w[b] slice
    __shared__ float rbfn_sh[CNC * CSFD];      // 4 KB
    __shared__ float cen_sh[CDIM * CNC];       // 192 B
    __shared__ float x_sh[PTS * CSFD];         // 8 KB : fused x = fl * sp_sum
    __shared__ float feat_sh[PTS * CK * 4];    // 8 KB : features padded to float4/k

    const int tid = threadIdx.x;
    const int b   = blockIdx.y;
    const int p0  = blockIdx.x * PTS;

    // ---- stage per-batch weight slice + constants + features into smem ----
    {
        const float4* wsrc = reinterpret_cast<const float4*>(w + (size_t)b * CSFD * COUT);
        float4* wdst = reinterpret_cast<float4*>(w_sh);
        #pragma unroll
        for (int i = 0; i < (CSFD * COUT / 4) / THREADS; i++)   // 4 iters
            wdst[tid + i * THREADS] = wsrc[tid + i * THREADS];

        reinterpret_cast<float4*>(rbfn_sh)[tid] =
            reinterpret_cast<const float4*>(rbfw)[tid];   // 256 float4 exactly

        // features: 32 pts x 48 floats = 384 float4, scatter to padded [pt][k][4]
        #pragma unroll
        for (int i = tid; i < PTS * FPP / 4; i += THREADS) {
            float4 v = reinterpret_cast<const float4*>(
                features + ((size_t)b * CP + p0) * FPP)[i];
            int f0 = 4 * i;
            #pragma unroll
            for (int e = 0; e < 4; e++) {
                int f  = f0 + e;
                int pt = f / FPP;
                int r  = f - pt * FPP;
                int k  = r / 3;
                int d  = r - k * 3;
                float val = (e == 0) ? v.x : (e == 1) ? v.y : (e == 2) ? v.z : v.w;
                feat_sh[(pt * CK + k) * 4 + d] = val;
            }
        }

        if (tid < CDIM * CNC) cen_sh[tid] = centers[tid];
    }
    __syncthreads();

    const int warp = tid >> 5;
    const int lane = tid & 31;
    const int cg   = lane & 15;   // column group (s = 4*cg..4*cg+3) AND center id
    const int half = lane >> 4;   // which half of the K rows this lane covers

    // ---- Phase 1: two passes of 2 points per warp (4 pts/warp total) ----
    #pragma unroll
    for (int pass = 0; pass < 2; pass++) {
        const int ptb = warp * 4 + pass * 2;   // local point base for this pass

        // --- 1a: spatial sums, 2 points interleaved ---
        float sx0 = 0.f, sy0 = 0.f, sz0 = 0.f, sw0 = 0.f;
        float sx1 = 0.f, sy1 = 0.f, sz1 = 0.f, sw1 = 0.f;

        const float4* spv = reinterpret_cast<const float4*>(
            spatial + ((size_t)b * CP + p0 + ptb) * (CK * CSFD));
        #pragma unroll
        for (int i = 0; i < 8; i++) {
            float4 v0 = spv[i * 32 + lane];
            float4 v1 = spv[256 + i * 32 + lane];
            sx0 += v0.x; sy0 += v0.y; sz0 += v0.z; sw0 += v0.w;
            sx1 += v1.x; sy1 += v1.y; sz1 += v1.z; sw1 += v1.w;
        }
        sx0 += __shfl_xor_sync(0xffffffffu, sx0, 16);
        sy0 += __shfl_xor_sync(0xffffffffu, sy0, 16);
        sz0 += __shfl_xor_sync(0xffffffffu, sz0, 16);
        sw0 += __shfl_xor_sync(0xffffffffu, sw0, 16);
        sx1 += __shfl_xor_sync(0xffffffffu, sx1, 16);
        sy1 += __shfl_xor_sync(0xffffffffu, sy1, 16);
        sz1 += __shfl_xor_sync(0xffffffffu, sz1, 16);
        sw1 += __shfl_xor_sync(0xffffffffu, sw1, 16);

        // --- 1b: RBF sums. lane -> center cg, covers 8 k's of its half ---
        const float c0 = cen_sh[0 * CNC + cg];
        const float c1 = cen_sh[1 * CNC + cg];
        const float c2 = cen_sh[2 * CNC + cg];

        float racc0 = 0.f, racc1 = 0.f;
        #pragma unroll
        for (int i = 0; i < 8; i++) {
            const int k = 2 * i + half;
            float4 f0 = reinterpret_cast<const float4*>(feat_sh)[(ptb + 0) * CK + k];
            float4 f1 = reinterpret_cast<const float4*>(feat_sh)[(ptb + 1) * CK + k];
            float a0 = f0.x - c0, a1 = f0.y - c1, a2 = f0.z - c2;
            float b0 = f1.x - c0, b1 = f1.y - c1, b2 = f1.z - c2;
            racc0 += __expf((a0 * a0 + a1 * a1 + a2 * a2) * -12.5f);
            racc1 += __expf((b0 * b0 + b1 * b1 + b2 * b2) * -12.5f);
        }
        racc0 += __shfl_xor_sync(0xffffffffu, racc0, 16);
        racc1 += __shfl_xor_sync(0xffffffffu, racc1, 16);
        // lane c (and c+16) now holds rbf_sum for center c

        // --- 1c: feature layer; ONE rbfn row live at a time, reused by both pts ---
        float flx0 = 0.f, fly0 = 0.f, flz0 = 0.f, flw0 = 0.f;
        float flx1 = 0.f, fly1 = 0.f, flz1 = 0.f, flw1 = 0.f;
        #pragma unroll
        for (int c = 0; c < CNC; c++) {
            float4 wv = reinterpret_cast<const float4*>(rbfn_sh)[c * 16 + cg];
            float r0 = __shfl_sync(0xffffffffu, racc0, c);
            float r1 = __shfl_sync(0xffffffffu, racc1, c);
            flx0 += r0 * wv.x; fly0 += r0 * wv.y; flz0 += r0 * wv.z; flw0 += r0 * wv.w;
            flx1 += r1 * wv.x; fly1 += r1 * wv.y; flz1 += r1 * wv.z; flw1 += r1 * wv.w;
        }
        if (half == 0) {
            float4 xv0, xv1;
            xv0.x = flx0 * sx0; xv0.y = fly0 * sy0; xv0.z = flz0 * sz0; xv0.w = flw0 * sw0;
            xv1.x = flx1 * sx1; xv1.y = fly1 * sy1; xv1.z = flz1 * sz1; xv1.w = flw1 * sw1;
            reinterpret_cast<float4*>(x_sh)[(ptb + 0) * 16 + cg] = xv0;
            reinterpret_cast<float4*>(x_sh)[(ptb + 1) * 16 + cg] = xv1;
        }
    }
    __syncthreads();

    // ---- Phase 2: out[pt][o] = sum_s x[pt][s] * w_sh[s][o], 8 pts/thread ----
    const int o  = tid & 63;
    const int pg = tid >> 6;   // 0..3, each group handles 8 points

    float acc[8];
    #pragma unroll
    for (int jj = 0; jj < 8; jj++) acc[jj] = 0.f;

    #pragma unroll
    for (int sq = 0; sq < CSFD / 4; sq++) {
        float w0 = w_sh[(4 * sq + 0) * COUT + o];
        float w1 = w_sh[(4 * sq + 1) * COUT + o];
        float w2 = w_sh[(4 * sq + 2) * COUT + o];
        float w3 = w_sh[(4 * sq + 3) * COUT + o];
        #pragma unroll
        for (int jj = 0; jj < 8; jj++) {
            // warp-uniform address -> smem broadcast (1 wavefront)
            float4 xv = reinterpret_cast<const float4*>(x_sh)[(pg * 8 + jj) * 16 + sq];
            acc[jj] += xv.x * w0 + xv.y * w1 + xv.z * w2 + xv.w * w3;
        }
    }

    float* ob = out + ((size_t)b * CP + p0) * COUT;
    #pragma unroll
    for (int jj = 0; jj < 8; jj++)
        ob[(size_t)(pg * 8 + jj) * COUT + o] = acc[jj];
}

extern "C" void kernel_launch(void* const* d_in, const int* in_sizes, int n_in,
                              void* d_out, int out_size)
{
    const float* features = (const float*)d_in[0];
    const float* spatial  = (const float*)d_in[1];
    const float* centers  = (const float*)d_in[2];
    const float* rbfw     = (const float*)d_in[3];
    const float* w        = (const float*)d_in[4];
    // d_in[5] is K (=16), fixed at compile time
    float* out = (float*)d_out;

    dim3 grid(CP / PTS, CB);
    rbfn_fused_kernel<<<grid, THREADS>>>(features, spatial, centers, rbfw, w, out);
}

// round 9
// speedup vs baseline: 1.4695x; 1.4615x over previous
#include <cuda_runtime.h>
#include <cstddef>

// Problem constants (fixed by the reference)
constexpr int CB   = 64;    // batch
constexpr int CP   = 2048;  // points
constexpr int CK   = 16;    // neighbors
constexpr int CDIM = 3;
constexpr int CNC  = 16;    // rbf centers
constexpr int CSFD = 64;    // spatial feature dim
constexpr int COUT = 64;    // output features

constexpr int PTS     = 32;   // points per block
constexpr int THREADS = 256;  // 8 warps; phase 1: 2 pts/warp x 2 sequential passes
constexpr int FPP     = CK * CDIM;  // 48 floats of features per point

__global__ __launch_bounds__(THREADS, 3)
void rbfn_fused_kernel(const float* __restrict__ features,
                       const float* __restrict__ spatial,
                       const float* __restrict__ centers,
                       const float* __restrict__ rbfw,
                       const float* __restrict__ w,
                       float* __restrict__ out)
{
    __shared__ float w_sh[CSFD * COUT];        // 16 KB : w[b] slice
    __shared__ float rbfn_sh[CNC * CSFD];      // 4 KB
    __shared__ float cen_sh[CDIM * CNC];       // 192 B
    __shared__ float x_sh[PTS * CSFD];         // 8 KB : fused x = fl * sp_sum
    __shared__ float feat_sh[PTS * CK * 4];    // 8 KB : features padded to float4/k

    const int tid = threadIdx.x;
    const int b   = blockIdx.y;
    const int p0  = blockIdx.x * PTS;

    // ---- stage per-batch weight slice + constants + features into smem ----
    {
        const float4* wsrc = reinterpret_cast<const float4*>(w + (size_t)b * CSFD * COUT);
        float4* wdst = reinterpret_cast<float4*>(w_sh);
        #pragma unroll
        for (int i = 0; i < (CSFD * COUT / 4) / THREADS; i++)   // 4 iters
            wdst[tid + i * THREADS] = wsrc[tid + i * THREADS];

        reinterpret_cast<float4*>(rbfn_sh)[tid] =
            reinterpret_cast<const float4*>(rbfw)[tid];   // 256 float4 exactly

        // features: 32 pts x 48 floats = 384 float4, scatter to padded [pt][k][4]
        #pragma unroll
        for (int i = tid; i < PTS * FPP / 4; i += THREADS) {
            float4 v = reinterpret_cast<const float4*>(
                features + ((size_t)b * CP + p0) * FPP)[i];
            int f0 = 4 * i;
            #pragma unroll
            for (int e = 0; e < 4; e++) {
                int f  = f0 + e;
                int pt = f / FPP;
                int r  = f - pt * FPP;
                int k  = r / 3;
                int d  = r - k * 3;
                float val = (e == 0) ? v.x : (e == 1) ? v.y : (e == 2) ? v.z : v.w;
                feat_sh[(pt * CK + k) * 4 + d] = val;
            }
        }

        if (tid < CDIM * CNC) cen_sh[tid] = centers[tid];
    }
    __syncthreads();

    const int warp = tid >> 5;
    const int lane = tid & 31;
    const int cg   = lane & 15;   // column group (s = 4*cg..4*cg+3) AND center id
    const int half = lane >> 4;   // which half of the K rows this lane covers

    // ---- Phase 1: two SEQUENTIAL passes of 2 points per warp ----
    // unroll 1: only one pass's live set exists at a time (register pressure)
    #pragma unroll 1
    for (int pass = 0; pass < 2; pass++) {
        const int ptb = warp * 4 + pass * 2;   // local point base for this pass

        // --- 1a: spatial sums, 2 points interleaved ---
        float sx0 = 0.f, sy0 = 0.f, sz0 = 0.f, sw0 = 0.f;
        float sx1 = 0.f, sy1 = 0.f, sz1 = 0.f, sw1 = 0.f;

        const float4* spv = reinterpret_cast<const float4*>(
            spatial + ((size_t)b * CP + p0 + ptb) * (CK * CSFD));
        #pragma unroll
        for (int i = 0; i < 8; i++) {
            float4 v0 = spv[i * 32 + lane];
            float4 v1 = spv[256 + i * 32 + lane];
            sx0 += v0.x; sy0 += v0.y; sz0 += v0.z; sw0 += v0.w;
            sx1 += v1.x; sy1 += v1.y; sz1 += v1.z; sw1 += v1.w;
        }
        sx0 += __shfl_xor_sync(0xffffffffu, sx0, 16);
        sy0 += __shfl_xor_sync(0xffffffffu, sy0, 16);
        sz0 += __shfl_xor_sync(0xffffffffu, sz0, 16);
        sw0 += __shfl_xor_sync(0xffffffffu, sw0, 16);
        sx1 += __shfl_xor_sync(0xffffffffu, sx1, 16);
        sy1 += __shfl_xor_sync(0xffffffffu, sy1, 16);
        sz1 += __shfl_xor_sync(0xffffffffu, sz1, 16);
        sw1 += __shfl_xor_sync(0xffffffffu, sw1, 16);

        // --- 1b: RBF sums. lane -> center cg, covers 8 k's of its half ---
        const float c0 = cen_sh[0 * CNC + cg];
        const float c1 = cen_sh[1 * CNC + cg];
        const float c2 = cen_sh[2 * CNC + cg];

        float racc0 = 0.f, racc1 = 0.f;
        #pragma unroll
        for (int i = 0; i < 8; i++) {
            const int k = 2 * i + half;
            float4 f0 = reinterpret_cast<const float4*>(feat_sh)[(ptb + 0) * CK + k];
            float4 f1 = reinterpret_cast<const float4*>(feat_sh)[(ptb + 1) * CK + k];
            float a0 = f0.x - c0, a1 = f0.y - c1, a2 = f0.z - c2;
            float b0 = f1.x - c0, b1 = f1.y - c1, b2 = f1.z - c2;
            racc0 += __expf((a0 * a0 + a1 * a1 + a2 * a2) * -12.5f);
            racc1 += __expf((b0 * b0 + b1 * b1 + b2 * b2) * -12.5f);
        }
        racc0 += __shfl_xor_sync(0xffffffffu, racc0, 16);
        racc1 += __shfl_xor_sync(0xffffffffu, racc1, 16);
        // lane c (and c+16) now holds rbf_sum for center c

        // --- 1c: feature layer; ONE rbfn row live at a time, reused by both pts ---
        float flx0 = 0.f, fly0 = 0.f, flz0 = 0.f, flw0 = 0.f;
        float flx1 = 0.f, fly1 = 0.f, flz1 = 0.f, flw1 = 0.f;
        #pragma unroll
        for (int c = 0; c < CNC; c++) {
            float4 wv = reinterpret_cast<const float4*>(rbfn_sh)[c * 16 + cg];
            float r0 = __shfl_sync(0xffffffffu, racc0, c);
            float r1 = __shfl_sync(0xffffffffu, racc1, c);
            flx0 += r0 * wv.x; fly0 += r0 * wv.y; flz0 += r0 * wv.z; flw0 += r0 * wv.w;
            flx1 += r1 * wv.x; fly1 += r1 * wv.y; flz1 += r1 * wv.z; flw1 += r1 * wv.w;
        }
        if (half == 0) {
            float4 xv0, xv1;
            xv0.x = flx0 * sx0; xv0.y = fly0 * sy0; xv0.z = flz0 * sz0; xv0.w = flw0 * sw0;
            xv1.x = flx1 * sx1; xv1.y = fly1 * sy1; xv1.z = flz1 * sz1; xv1.w = flw1 * sw1;
            reinterpret_cast<float4*>(x_sh)[(ptb + 0) * 16 + cg] = xv0;
            reinterpret_cast<float4*>(x_sh)[(ptb + 1) * 16 + cg] = xv1;
        }
    }
    __syncthreads();

    // ---- Phase 2: out[pt][o] = sum_s x[pt][s] * w_sh[s][o], 8 pts/thread ----
    const int o  = tid & 63;
    const int pg = tid >> 6;   // 0..3, each group handles 8 points

    float acc[8];
    #pragma unroll
    for (int jj = 0; jj < 8; jj++) acc[jj] = 0.f;

    #pragma unroll
    for (int sq = 0; sq < CSFD / 4; sq++) {
        float w0 = w_sh[(4 * sq + 0) * COUT + o];
        float w1 = w_sh[(4 * sq + 1) * COUT + o];
        float w2 = w_sh[(4 * sq + 2) * COUT + o];
        float w3 = w_sh[(4 * sq + 3) * COUT + o];
        #pragma unroll
        for (int jj = 0; jj < 8; jj++) {
            // warp-uniform address -> smem broadcast (1 wavefront)
            float4 xv = reinterpret_cast<const float4*>(x_sh)[(pg * 8 + jj) * 16 + sq];
            acc[jj] += xv.x * w0 + xv.y * w1 + xv.z * w2 + xv.w * w3;
        }
    }

    float* ob = out + ((size_t)b * CP + p0) * COUT;
    #pragma unroll
    for (int jj = 0; jj < 8; jj++)
        ob[(size_t)(pg * 8 + jj) * COUT + o] = acc[jj];
}

extern "C" void kernel_launch(void* const* d_in, const int* in_sizes, int n_in,
                              void* d_out, int out_size)
{
    const float* features = (const float*)d_in[0];
    const float* spatial  = (const float*)d_in[1];
    const float* centers  = (const float*)d_in[2];
    const float* rbfw     = (const float*)d_in[3];
    const float* w        = (const float*)d_in[4];
    // d_in[5] is K (=16), fixed at compile time
    float* out = (float*)d_out;

    dim3 grid(CP / PTS, CB);
    rbfn_fused_kernel<<<grid, THREADS>>>(features, spatial, centers, rbfw, w, out);
}